// round 15
// baseline (speedup 1.0000x reference)
#include <cuda_runtime.h>

#define TT 1024
#define BB 64
#define DD 256
#define HH 256
#define G4 1024
#define AA 128
#define MM 256

typedef unsigned long long u64;

// ---------------- packed fp32x2 helpers (sm_100+) ----------------
__device__ __forceinline__ u64 ffma2(u64 a, u64 b, u64 c) {
    u64 d;
    asm("fma.rn.f32x2 %0, %1, %2, %3;" : "=l"(d) : "l"(a), "l"(b), "l"(c));
    return d;
}
__device__ __forceinline__ u64 bcast2(float v) {
    u64 r;
    asm("mov.b64 %0, {%1, %1};" : "=l"(r) : "f"(v));
    return r;
}
__device__ __forceinline__ u64 pack2(float lo, float hi) {
    u64 r;
    asm("mov.b64 %0, {%1, %2};" : "=l"(r) : "f"(lo), "f"(hi));
    return r;
}
__device__ __forceinline__ float2 unpk(u64 v) {
    float2 f;
    asm("mov.b64 {%0, %1}, %2;" : "=f"(f.x), "=f"(f.y) : "l"(v));
    return f;
}

// ---------------- device scratch (allocation-free) ----------------
__device__ float d_GS[TT * BB * G4];   // stack-LSTM preacts x@Wsx+bs, [T,B,4H]
__device__ float d_GH[TT * BB * G4];   // hist-LSTM  preacts x@Whx+bh
__device__ float d_HS[TT * BB * HH];   // stack hidden states [T,B,H]
__device__ float d_HH_[TT * BB * HH];  // hist  hidden states
__device__ float d_hbuf[2 * 2 * BB * HH]; // [parity][lstm][B*H] h exchange
__device__ float d_partial[2048];
__device__ unsigned d_barrier[16];

// ===================================================================
// K1: gathered SGEMM.  out[n,:] = emb[id(n)] @ W + bias
//     n = t*64 + b ; id = ids[b*T + t]
// 128x64 tile, BK=16, 256 threads, 8x4 microtile, f32x2 packed rows.
// ===================================================================
__global__ __launch_bounds__(256) void embed_gemm(
    const int* __restrict__ stack_ids, const int* __restrict__ action_ids,
    const float* __restrict__ word_emb, const float* __restrict__ action_emb,
    const float* __restrict__ Wsx, const float* __restrict__ Whx,
    const float* __restrict__ bs, const float* __restrict__ bh)
{
    const int* ids; const float* emb; const float* W; const float* bias; float* out;
    if (blockIdx.z == 0) { ids = stack_ids;  emb = word_emb;   W = Wsx; bias = bs; out = d_GS; }
    else                 { ids = action_ids; emb = action_emb; W = Whx; bias = bh; out = d_GH; }

    __shared__ __align__(16) float As[16][132];
    __shared__ __align__(16) float Bs[16][68];
    __shared__ int rid[128];

    const int tid = threadIdx.x;
    const int n0  = blockIdx.x * 128;
    const int bn  = blockIdx.y * 64;

    if (tid < 128) {
        int n = n0 + tid;
        rid[tid] = ids[(n & 63) * TT + (n >> 6)];
    }
    __syncthreads();

    const int tx = tid & 15;
    const int ty = tid >> 4;
    u64 accP[4][4];                       // [row-pair][col], packed (row0,row1)
    #pragma unroll
    for (int i = 0; i < 4; ++i)
        #pragma unroll
        for (int j = 0; j < 4; ++j) accP[i][j] = 0ull;

    for (int kt = 0; kt < DD; kt += 16) {
        {   // A tile (gathered embedding rows)
            int kk = tid & 15, mb = tid >> 4;
            #pragma unroll
            for (int p = 0; p < 8; ++p) {
                int m = mb + p * 16;
                As[kk][m] = emb[(size_t)rid[m] * DD + kt + kk];
            }
        }
        {   // B tile
            int nn = tid & 63, kb = tid >> 6;
            #pragma unroll
            for (int p = 0; p < 4; ++p) {
                int kk = kb + p * 4;
                Bs[kk][nn] = W[(size_t)(kt + kk) * G4 + bn + nn];
            }
        }
        __syncthreads();
        #pragma unroll
        for (int k = 0; k < 16; ++k) {
            ulonglong2 a01 = *(const ulonglong2*)&As[k][ty * 8];
            ulonglong2 a23 = *(const ulonglong2*)&As[k][ty * 8 + 4];
            u64 ap[4] = {a01.x, a01.y, a23.x, a23.y};
            float4 b4 = *(const float4*)&Bs[k][tx * 4];
            u64 bb[4] = {bcast2(b4.x), bcast2(b4.y), bcast2(b4.z), bcast2(b4.w)};
            #pragma unroll
            for (int i = 0; i < 4; ++i)
                #pragma unroll
                for (int j = 0; j < 4; ++j)
                    accP[i][j] = ffma2(ap[i], bb[j], accP[i][j]);
        }
        __syncthreads();
    }

    #pragma unroll
    for (int i = 0; i < 4; ++i) {
        int n = n0 + ty * 8 + 2 * i;
        float* r0 = out + (size_t)n * G4 + bn + tx * 4;
        float* r1 = r0 + G4;
        #pragma unroll
        for (int j = 0; j < 4; ++j) {
            float2 v = unpk(accP[i][j]);
            float bbv = bias[bn + tx * 4 + j];
            r0[j] = v.x + bbv;
            r1[j] = v.y + bbv;
        }
    }
}

// ===================================================================
// K2: persistent LSTM recurrence. 128 CTAs x 256 threads.
//   Group = (L,bbg): 8 CTAs, per-group atomic barrier, h via gmem dbl-buffer.
//   Phase A: Wh fragment pre-packed along k into f32x2 pairs (in regs).
// ===================================================================
__global__ __launch_bounds__(256, 1) void lstm_rec(
    const float* __restrict__ Wsh, const float* __restrict__ Whh)
{
    const int bx  = blockIdx.x;
    const int L   = bx >> 6;
    const int cid = bx & 63;
    const int bbg = cid >> 3;
    const int jb  = cid & 7;
    const int gid = L * 8 + bbg;

    const float* __restrict__ Wh = L ? Whh  : Wsh;
    const float* __restrict__ G  = L ? d_GH : d_GS;
    float* __restrict__ Hout     = L ? d_HH_ : d_HS;

    const int tid   = threadIdx.x;
    const int ks    = tid >> 5;   // k-slice (phase A)
    const int cg    = tid & 31;   // 4-col group (phase A)
    const int b_loc = tid >> 5;   // batch (phase B)
    const int jl    = tid & 31;   // hidden col (phase B)
    const int bglob = bbg * 8 + b_loc;
    const int j     = jb * 32 + jl;

    __shared__ __align__(16) float hsm[8 * 256];
    __shared__ float4 part[8][8][32];   // [ks][b][cg]

    // persistent Wh fragment, packed along k: Wp[c][q] = (W[2q], W[2q+1])
    u64 Wp[4][16];
    #pragma unroll
    for (int c = 0; c < 4; ++c) {
        int cc   = cg * 4 + c;
        int gcol = (cc >> 5) * 256 + jb * 32 + (cc & 31);
        const float* wp = Wh + (size_t)ks * 32 * G4 + gcol;
        #pragma unroll
        for (int q = 0; q < 16; ++q)
            Wp[c][q] = pack2(wp[(size_t)(2 * q) * G4], wp[(size_t)(2 * q + 1) * G4]);
    }

    for (int i = tid; i < 2048; i += 256) hsm[i] = 0.0f;
    float cst = 0.0f;
    __syncthreads();

    const float* Gbase = G + (size_t)bglob * G4 + j;

    for (int t = 0; t < TT; ++t) {
        // prefetch this step's input preacts (used in phase B)
        size_t go = (size_t)t * BB * G4;
        float gp0 = Gbase[go];
        float gp1 = Gbase[go + 256];
        float gp2 = Gbase[go + 512];
        float gp3 = Gbase[go + 768];

        // ---- Phase A: packed partial dot products
        for (int b = 0; b < 8; ++b) {
            const u64* hp = (const u64*)(hsm + b * 256 + ks * 32);  // 16 k-pairs
            u64 a0 = 0ull, a1 = 0ull, a2 = 0ull, a3 = 0ull;
            #pragma unroll
            for (int q = 0; q < 16; ++q) {
                u64 h2 = hp[q];
                a0 = ffma2(h2, Wp[0][q], a0);
                a1 = ffma2(h2, Wp[1][q], a1);
                a2 = ffma2(h2, Wp[2][q], a2);
                a3 = ffma2(h2, Wp[3][q], a3);
            }
            float2 r0 = unpk(a0), r1 = unpk(a1), r2 = unpk(a2), r3 = unpk(a3);
            part[ks][b][cg] = make_float4(r0.x + r0.y, r1.x + r1.y,
                                          r2.x + r2.y, r3.x + r3.y);
        }
        __syncthreads();

        // ---- Phase B: reduce + gates
        float gv[4] = {gp0, gp1, gp2, gp3};
        const float* pf = (const float*)part;
        #pragma unroll
        for (int g = 0; g < 4; ++g) {
            int cc  = g * 32 + jl;
            int cg2 = cc >> 2;
            int c2  = cc & 3;
            float s = 0.0f;
            #pragma unroll
            for (int k2 = 0; k2 < 8; ++k2)
                s += pf[((k2 * 8 + b_loc) * 32 + cg2) * 4 + c2];
            gv[g] += s;
        }
        float iv = 1.0f / (1.0f + __expf(-gv[0]));
        float fv = 1.0f / (1.0f + __expf(-gv[1]));
        float gg = tanhf(gv[2]);
        float ov = 1.0f / (1.0f + __expf(-gv[3]));
        cst = fv * cst + iv * gg;
        float h = ov * tanhf(cst);

        Hout[((size_t)t * BB + bglob) * HH + j] = h;
        __stcg(&d_hbuf[(((t & 1) * 2 + L) * BB + bglob) * HH + j], h);

        if (t + 1 < TT) {
            __threadfence();
            __syncthreads();
            if (tid == 0) {
                atomicAdd(&d_barrier[gid], 1u);
                unsigned target = 8u * (unsigned)(t + 1);
                while (*(volatile unsigned*)&d_barrier[gid] < target) { }
            }
            __syncthreads();
            const float4* src = (const float4*)
                (d_hbuf + ((size_t)((t & 1) * 2 + L) * BB + bbg * 8) * HH);
            for (int i = tid; i < 512; i += 256)
                *((float4*)hsm + i) = __ldcg(src + i);
            __syncthreads();
        }
    }
}

// ===================================================================
// K3: MLP + NLL. One CTA = one t x 32 batches.
//   x = [word_emb[buffer_ids] | h_hist(t-1) | h_stack(t-1)] (768)
// ===================================================================
__global__ __launch_bounds__(256) void mlp_nll(
    const int* __restrict__ buffer_ids, const int* __restrict__ action_ids,
    const float* __restrict__ word_emb,
    const float* __restrict__ W1, const float* __restrict__ b1,
    const float* __restrict__ W2, const float* __restrict__ b2)
{
    const int tid   = threadIdx.x;
    const int t     = blockIdx.x >> 1;
    const int bhalf = (blockIdx.x & 1) * 32;

    __shared__ __align__(16) char uni[32896];
    float (*As)[36]   = (float(*)[36])uni;               // 2304 B
    float (*Bs)[256]  = (float(*)[256])(uni + 2304);     // 16384 B
    float (*ysm)[257] = (float(*)[257])uni;              // 32896 B (overlays A/B)
    float (*zsm)[133] = (float(*)[133])uni;              // 17024 B (overlays ysm)
    __shared__ __align__(16) float w2s[16][128];
    __shared__ int bid_s[32], aid_s[32];

    if (tid < 32) {
        bid_s[tid] = buffer_ids[(bhalf + tid) * TT + t];
        aid_s[tid] = action_ids[(bhalf + tid) * TT + t];
    }
    __syncthreads();

    // ---- GEMM1: [32 x 768] @ [768 x 256]
    // thread (tx,ry): rows {ry*2, ry*2+1}, cols {ch*64 + tx*4 + jc}, ch 0..3
    const int tx = tid & 15;
    const int ry = tid >> 4;
    u64 accP[2][8];                // [row][ch*2 + colpair]
    #pragma unroll
    for (int i = 0; i < 2; ++i)
        #pragma unroll
        for (int jj = 0; jj < 8; ++jj) accP[i][jj] = 0ull;

    for (int kt = 0; kt < 768; kt += 16) {
        {   // A tile: assemble x columns (seg 0: buf emb, 1: hist h, 2: stack h)
            int kk = tid & 15, rb = tid >> 4;
            int seg  = kt >> 8;
            int kloc = (kt & 255) + kk;
            #pragma unroll
            for (int p = 0; p < 2; ++p) {
                int r = rb + p * 16;
                float v;
                if (seg == 0) {
                    v = word_emb[(size_t)bid_s[r] * DD + kloc];
                } else if (t == 0) {
                    v = 0.0f;
                } else {
                    const float* H = (seg == 1) ? d_HH_ : d_HS;
                    v = H[((size_t)(t - 1) * BB + bhalf + r) * HH + kloc];
                }
                As[kk][r] = v;
            }
        }
        for (int i = tid; i < 4096; i += 256) {
            int kk = i >> 8, col = i & 255;
            Bs[kk][col] = W1[(size_t)(kt + kk) * MM + col];
        }
        __syncthreads();
        #pragma unroll
        for (int k = 0; k < 16; ++k) {
            u64 A0 = bcast2(As[k][ry * 2]);
            u64 A1 = bcast2(As[k][ry * 2 + 1]);
            #pragma unroll
            for (int ch = 0; ch < 4; ++ch) {
                ulonglong2 w = *(const ulonglong2*)&Bs[k][ch * 64 + tx * 4];
                accP[0][ch * 2]     = ffma2(A0, w.x, accP[0][ch * 2]);
                accP[0][ch * 2 + 1] = ffma2(A0, w.y, accP[0][ch * 2 + 1]);
                accP[1][ch * 2]     = ffma2(A1, w.x, accP[1][ch * 2]);
                accP[1][ch * 2 + 1] = ffma2(A1, w.y, accP[1][ch * 2 + 1]);
            }
        }
        __syncthreads();
    }

    // relu(y + b1) -> ysm (A/B tiles dead after last sync)
    #pragma unroll
    for (int ch = 0; ch < 4; ++ch) {
        #pragma unroll
        for (int cp = 0; cp < 2; ++cp) {
            int col = ch * 64 + tx * 4 + cp * 2;
            float bb0 = b1[col], bb1 = b1[col + 1];
            #pragma unroll
            for (int i = 0; i < 2; ++i) {
                float2 v = unpk(accP[i][ch * 2 + cp]);
                float v0 = v.x + bb0; v0 = v0 > 0.0f ? v0 : 0.0f;
                float v1 = v.y + bb1; v1 = v1 > 0.0f ? v1 : 0.0f;
                ysm[ry * 2 + i][col]     = v0;
                ysm[ry * 2 + i][col + 1] = v1;
            }
        }
    }
    __syncthreads();

    // ---- GEMM2: [32 x 256] @ [256 x 128]
    // thread (c32,rz): rows {rz*4..+3}, cols {c32*4..+3}
    const int c32 = tid & 31;
    const int rz  = tid >> 5;
    u64 acc2[4][2];
    #pragma unroll
    for (int i = 0; i < 4; ++i) { acc2[i][0] = 0ull; acc2[i][1] = 0ull; }

    for (int kt = 0; kt < 256; kt += 16) {
        for (int i = tid; i < 2048; i += 256) {
            int kk = i >> 7, col = i & 127;
            w2s[kk][col] = W2[(size_t)(kt + kk) * AA + col];
        }
        __syncthreads();
        #pragma unroll
        for (int k = 0; k < 16; ++k) {
            ulonglong2 w = *(const ulonglong2*)&w2s[k][c32 * 4];
            #pragma unroll
            for (int i = 0; i < 4; ++i) {
                u64 a2 = bcast2(ysm[rz * 4 + i][kt + k]);
                acc2[i][0] = ffma2(a2, w.x, acc2[i][0]);
                acc2[i][1] = ffma2(a2, w.y, acc2[i][1]);
            }
        }
        __syncthreads();
    }

    // z -> zsm (ysm dead after last sync)
    {
        int col = c32 * 4;
        float b20 = b2[col], b21 = b2[col + 1], b22 = b2[col + 2], b23 = b2[col + 3];
        #pragma unroll
        for (int i = 0; i < 4; ++i) {
            float2 v0 = unpk(acc2[i][0]);
            float2 v1 = unpk(acc2[i][1]);
            zsm[rz * 4 + i][col]     = v0.x + b20;
            zsm[rz * 4 + i][col + 1] = v0.y + b21;
            zsm[rz * 4 + i][col + 2] = v1.x + b22;
            zsm[rz * 4 + i][col + 3] = v1.y + b23;
        }
    }
    __syncthreads();

    // ---- per-row log-softmax NLL (warp 0, one thread per row)
    if (tid < 32) {
        float mx = -1e30f;
        for (int c = 0; c < 128; ++c) mx = fmaxf(mx, zsm[tid][c]);
        float se = 0.0f;
        for (int c = 0; c < 128; ++c) se += expf(zsm[tid][c] - mx);
        float nll = mx + logf(se) - zsm[tid][aid_s[tid]];
        #pragma unroll
        for (int o = 16; o; o >>= 1)
            nll += __shfl_down_sync(0xffffffffu, nll, o);
        if (tid == 0) d_partial[blockIdx.x] = nll;
    }
}

// ===================================================================
// K4: deterministic final reduce
// ===================================================================
__global__ void reduce_k(float* __restrict__ out)
{
    __shared__ float s[256];
    float v = 0.0f;
    for (int i = threadIdx.x; i < 2048; i += 256) v += d_partial[i];
    s[threadIdx.x] = v;
    __syncthreads();
    for (int o = 128; o; o >>= 1) {
        if (threadIdx.x < o) s[threadIdx.x] += s[threadIdx.x + o];
        __syncthreads();
    }
    if (threadIdx.x == 0) out[0] = s[0];
}

// ===================================================================
extern "C" void kernel_launch(void* const* d_in, const int* in_sizes, int n_in,
                              void* d_out, int out_size)
{
    const int*   stack_ids  = (const int*)d_in[0];
    const int*   buffer_ids = (const int*)d_in[1];
    const int*   action_ids = (const int*)d_in[2];
    const float* word_emb   = (const float*)d_in[3];
    const float* action_emb = (const float*)d_in[4];
    const float* Wsx        = (const float*)d_in[5];
    const float* Wsh        = (const float*)d_in[6];
    const float* bs         = (const float*)d_in[7];
    const float* Whx        = (const float*)d_in[8];
    const float* Whh        = (const float*)d_in[9];
    const float* bh         = (const float*)d_in[10];
    const float* W1         = (const float*)d_in[11];
    const float* b1         = (const float*)d_in[12];
    const float* W2         = (const float*)d_in[13];
    const float* b2         = (const float*)d_in[14];
    float* out = (float*)d_out;

    void* barp = nullptr;
    cudaGetSymbolAddress(&barp, d_barrier);
    cudaMemsetAsync(barp, 0, 16 * sizeof(unsigned), 0);

    dim3 g1(512, 16, 2);
    embed_gemm<<<g1, 256>>>(stack_ids, action_ids, word_emb, action_emb,
                            Wsx, Whx, bs, bh);
    lstm_rec<<<128, 256>>>(Wsh, Whh);
    mlp_nll<<<2048, 256>>>(buffer_ids, action_ids, word_emb, W1, b1, W2, b2);
    reduce_k<<<1, 256>>>(out);
}

// round 17
// speedup vs baseline: 1.3937x; 1.3937x over previous
#include <cuda_runtime.h>

#define TT 1024
#define BB 64
#define DD 256
#define HH 256
#define G4 1024
#define AA 128
#define MM 256

// ---------------- device scratch (allocation-free) ----------------
__device__ float d_GS[32000 * G4];     // per-vocab stack preact table word_emb@Wsx+bs
__device__ float d_GH[AA * G4];        // per-action hist preact table action_emb@Whx+bh
__device__ float d_HS[TT * BB * HH];   // stack hidden states [T,B,H]
__device__ float d_HH_[TT * BB * HH];  // hist  hidden states
__device__ float d_hbuf[2 * 2 * BB * HH]; // [parity][lstm][B*H] h exchange
__device__ float d_partial[2048];
__device__ unsigned d_barrier[16];

// ===================================================================
// K1: dense SGEMM table build.  out[r,:] = E[r,:] @ W + bias
// 128x64 tile, BK=16, 256 threads, 8x4 microtile (scalar fp32).
// ===================================================================
__global__ __launch_bounds__(256) void table_gemm(
    const float* __restrict__ E, const float* __restrict__ W,
    const float* __restrict__ bias, float* __restrict__ out)
{
    __shared__ __align__(16) float As[16][132];
    __shared__ __align__(16) float Bs[16][68];

    const int tid = threadIdx.x;
    const int n0  = blockIdx.x * 128;
    const int bn  = blockIdx.y * 64;

    const int tx = tid & 15;
    const int ty = tid >> 4;
    float acc[8][4];
    #pragma unroll
    for (int i = 0; i < 8; ++i)
        #pragma unroll
        for (int j = 0; j < 4; ++j) acc[i][j] = 0.0f;

    for (int kt = 0; kt < DD; kt += 16) {
        {   // A tile (dense rows)
            int kk = tid & 15, mb = tid >> 4;
            #pragma unroll
            for (int p = 0; p < 8; ++p) {
                int m = mb + p * 16;
                As[kk][m] = E[(size_t)(n0 + m) * DD + kt + kk];
            }
        }
        {   // B tile
            int nn = tid & 63, kb = tid >> 6;
            #pragma unroll
            for (int p = 0; p < 4; ++p) {
                int kk = kb + p * 4;
                Bs[kk][nn] = W[(size_t)(kt + kk) * G4 + bn + nn];
            }
        }
        __syncthreads();
        #pragma unroll
        for (int k = 0; k < 16; ++k) {
            float4 a0 = *(const float4*)&As[k][ty * 8];
            float4 a1 = *(const float4*)&As[k][ty * 8 + 4];
            float4 b4 = *(const float4*)&Bs[k][tx * 4];
            float av[8] = {a0.x, a0.y, a0.z, a0.w, a1.x, a1.y, a1.z, a1.w};
            float bv[4] = {b4.x, b4.y, b4.z, b4.w};
            #pragma unroll
            for (int i = 0; i < 8; ++i)
                #pragma unroll
                for (int j = 0; j < 4; ++j)
                    acc[i][j] = fmaf(av[i], bv[j], acc[i][j]);
        }
        __syncthreads();
    }

    #pragma unroll
    for (int i = 0; i < 8; ++i) {
        int n = n0 + ty * 8 + i;
        float* orow = out + (size_t)n * G4 + bn + tx * 4;
        #pragma unroll
        for (int j = 0; j < 4; ++j)
            orow[j] = acc[i][j] + bias[bn + tx * 4 + j];
    }
}

// ===================================================================
// K2: persistent LSTM recurrence. 128 CTAs x 256 threads.
//   Group = (L,bbg): 8 CTAs, per-group atomic barrier, h via gmem dbl-buffer.
//   Input preacts gathered from per-id tables (d_GS by stack id, d_GH by action id).
// ===================================================================
__global__ __launch_bounds__(256, 1) void lstm_rec(
    const float* __restrict__ Wsh, const float* __restrict__ Whh,
    const int* __restrict__ stack_ids, const int* __restrict__ action_ids)
{
    const int bx  = blockIdx.x;
    const int L   = bx >> 6;
    const int cid = bx & 63;
    const int bbg = cid >> 3;
    const int jb  = cid & 7;
    const int gid = L * 8 + bbg;

    const float* __restrict__ Wh   = L ? Whh  : Wsh;
    const float* __restrict__ Gtab = L ? d_GH : d_GS;
    const int*   __restrict__ idsP = L ? action_ids : stack_ids;
    float* __restrict__ Hout       = L ? d_HH_ : d_HS;

    const int tid   = threadIdx.x;
    const int ks    = tid >> 5;   // k-slice (phase A)
    const int cg    = tid & 31;   // 4-col group (phase A)
    const int b_loc = tid >> 5;   // batch (phase B)
    const int jl    = tid & 31;   // hidden col (phase B)
    const int bglob = bbg * 8 + b_loc;
    const int j     = jb * 32 + jl;

    __shared__ __align__(16) float hsm[8 * 256];
    __shared__ float4 part[8][8][32];   // [ks][b][cg]

    // persistent Wh fragment in registers: 4 cols x 32 k
    float Wreg[4][32];
    #pragma unroll
    for (int c = 0; c < 4; ++c) {
        int cc   = cg * 4 + c;
        int gcol = (cc >> 5) * 256 + jb * 32 + (cc & 31);
        const float* wp = Wh + (size_t)ks * 32 * G4 + gcol;
        #pragma unroll
        for (int kk = 0; kk < 32; ++kk)
            Wreg[c][kk] = wp[(size_t)kk * G4];
    }

    for (int i = tid; i < 2048; i += 256) hsm[i] = 0.0f;
    float cst = 0.0f;
    __syncthreads();

    const int* idrow = idsP + (size_t)bglob * TT;

    for (int t = 0; t < TT; ++t) {
        // gather this step's input preacts from the per-id table (used in phase B)
        int id = __ldg(&idrow[t]);
        const float* Grow = Gtab + (size_t)id * G4 + j;
        float gp0 = Grow[0];
        float gp1 = Grow[256];
        float gp2 = Grow[512];
        float gp3 = Grow[768];

        // ---- Phase A: partial dot products
        for (int b = 0; b < 8; ++b) {
            const float* hrow = hsm + b * 256 + ks * 32;
            float4 acc = make_float4(0.f, 0.f, 0.f, 0.f);
            #pragma unroll
            for (int q = 0; q < 8; ++q) {
                float4 hq = *(const float4*)(hrow + q * 4);
                float hv[4] = {hq.x, hq.y, hq.z, hq.w};
                #pragma unroll
                for (int u = 0; u < 4; ++u) {
                    acc.x = fmaf(hv[u], Wreg[0][q * 4 + u], acc.x);
                    acc.y = fmaf(hv[u], Wreg[1][q * 4 + u], acc.y);
                    acc.z = fmaf(hv[u], Wreg[2][q * 4 + u], acc.z);
                    acc.w = fmaf(hv[u], Wreg[3][q * 4 + u], acc.w);
                }
            }
            part[ks][b][cg] = acc;
        }
        __syncthreads();

        // ---- Phase B: reduce + gates
        float gv[4] = {gp0, gp1, gp2, gp3};
        const float* pf = (const float*)part;
        #pragma unroll
        for (int g = 0; g < 4; ++g) {
            int cc  = g * 32 + jl;
            int cg2 = cc >> 2;
            int c2  = cc & 3;
            float s = 0.0f;
            #pragma unroll
            for (int k2 = 0; k2 < 8; ++k2)
                s += pf[((k2 * 8 + b_loc) * 32 + cg2) * 4 + c2];
            gv[g] += s;
        }
        float iv = 1.0f / (1.0f + __expf(-gv[0]));
        float fv = 1.0f / (1.0f + __expf(-gv[1]));
        float gg = tanhf(gv[2]);
        float ov = 1.0f / (1.0f + __expf(-gv[3]));
        cst = fv * cst + iv * gg;
        float h = ov * tanhf(cst);

        Hout[((size_t)t * BB + bglob) * HH + j] = h;
        __stcg(&d_hbuf[(((t & 1) * 2 + L) * BB + bglob) * HH + j], h);

        if (t + 1 < TT) {
            __threadfence();
            __syncthreads();
            if (tid == 0) {
                atomicAdd(&d_barrier[gid], 1u);
                unsigned target = 8u * (unsigned)(t + 1);
                while (*(volatile unsigned*)&d_barrier[gid] < target) { }
            }
            __syncthreads();
            const float4* src = (const float4*)
                (d_hbuf + ((size_t)((t & 1) * 2 + L) * BB + bbg * 8) * HH);
            for (int i = tid; i < 512; i += 256)
                *((float4*)hsm + i) = __ldcg(src + i);
            __syncthreads();
        }
    }
}

// ===================================================================
// K3: MLP + NLL. One CTA = one t x 32 batches.
//   x = [word_emb[buffer_ids] | h_hist(t-1) | h_stack(t-1)] (768)
// ===================================================================
__global__ __launch_bounds__(256) void mlp_nll(
    const int* __restrict__ buffer_ids, const int* __restrict__ action_ids,
    const float* __restrict__ word_emb,
    const float* __restrict__ W1, const float* __restrict__ b1,
    const float* __restrict__ W2, const float* __restrict__ b2)
{
    const int tid   = threadIdx.x;
    const int t     = blockIdx.x >> 1;
    const int bhalf = (blockIdx.x & 1) * 32;

    __shared__ __align__(16) char uni[32896];
    float (*As)[36]   = (float(*)[36])uni;               // 2304 B
    float (*Bs)[256]  = (float(*)[256])(uni + 2304);     // 16384 B
    float (*ysm)[257] = (float(*)[257])uni;              // 32896 B (overlays A/B)
    float (*zsm)[133] = (float(*)[133])uni;              // 17024 B (overlays ysm)
    __shared__ __align__(16) float w2s[16][128];
    __shared__ int bid_s[32], aid_s[32];

    if (tid < 32) {
        bid_s[tid] = buffer_ids[(bhalf + tid) * TT + t];
        aid_s[tid] = action_ids[(bhalf + tid) * TT + t];
    }
    __syncthreads();

    // ---- GEMM1: [32 x 768] @ [768 x 256]
    const int tx = tid & 15;
    const int ry = tid >> 4;
    float acc[2][16];
    #pragma unroll
    for (int i = 0; i < 2; ++i)
        #pragma unroll
        for (int jj = 0; jj < 16; ++jj) acc[i][jj] = 0.0f;

    for (int kt = 0; kt < 768; kt += 16) {
        {   // A tile: assemble x columns (seg 0: buf emb, 1: hist h, 2: stack h)
            int kk = tid & 15, rb = tid >> 4;
            int seg  = kt >> 8;
            int kloc = (kt & 255) + kk;
            #pragma unroll
            for (int p = 0; p < 2; ++p) {
                int r = rb + p * 16;
                float v;
                if (seg == 0) {
                    v = word_emb[(size_t)bid_s[r] * DD + kloc];
                } else if (t == 0) {
                    v = 0.0f;
                } else {
                    const float* H = (seg == 1) ? d_HH_ : d_HS;
                    v = H[((size_t)(t - 1) * BB + bhalf + r) * HH + kloc];
                }
                As[kk][r] = v;
            }
        }
        for (int i = tid; i < 4096; i += 256) {
            int kk = i >> 8, col = i & 255;
            Bs[kk][col] = W1[(size_t)(kt + kk) * MM + col];
        }
        __syncthreads();
        #pragma unroll
        for (int k = 0; k < 16; ++k) {
            float a0 = As[k][ry * 2];
            float a1 = As[k][ry * 2 + 1];
            #pragma unroll
            for (int jj = 0; jj < 16; ++jj) {
                float w = Bs[k][tx + 16 * jj];
                acc[0][jj] = fmaf(a0, w, acc[0][jj]);
                acc[1][jj] = fmaf(a1, w, acc[1][jj]);
            }
        }
        __syncthreads();
    }

    // relu(y + b1) -> ysm (A/B tiles dead after last sync)
    #pragma unroll
    for (int jj = 0; jj < 16; ++jj) {
        int col = tx + 16 * jj;
        float bb = b1[col];
        float v0 = acc[0][jj] + bb; v0 = v0 > 0.0f ? v0 : 0.0f;
        float v1 = acc[1][jj] + bb; v1 = v1 > 0.0f ? v1 : 0.0f;
        ysm[ry * 2][col]     = v0;
        ysm[ry * 2 + 1][col] = v1;
    }
    __syncthreads();

    // ---- GEMM2: [32 x 256] @ [256 x 128], W2 staged in SMEM chunks
    const int c32 = tid & 31;
    const int rz  = tid >> 5;     // rows rz*4 .. rz*4+3
    float acc2[4][4];
    #pragma unroll
    for (int i = 0; i < 4; ++i)
        #pragma unroll
        for (int jj = 0; jj < 4; ++jj) acc2[i][jj] = 0.0f;

    for (int kt = 0; kt < 256; kt += 16) {
        for (int i = tid; i < 2048; i += 256) {
            int kk = i >> 7, col = i & 127;
            w2s[kk][col] = W2[(size_t)(kt + kk) * AA + col];
        }
        __syncthreads();
        #pragma unroll
        for (int k = 0; k < 16; ++k) {
            float a[4];
            #pragma unroll
            for (int i = 0; i < 4; ++i) a[i] = ysm[rz * 4 + i][kt + k];
            #pragma unroll
            for (int jj = 0; jj < 4; ++jj) {
                float w = w2s[k][c32 + 32 * jj];
                #pragma unroll
                for (int i = 0; i < 4; ++i)
                    acc2[i][jj] = fmaf(a[i], w, acc2[i][jj]);
            }
        }
        __syncthreads();
    }

    // z -> zsm (ysm dead after last sync)
    #pragma unroll
    for (int jj = 0; jj < 4; ++jj) {
        int col = c32 + 32 * jj;
        float bb2 = b2[col];
        #pragma unroll
        for (int i = 0; i < 4; ++i)
            zsm[rz * 4 + i][col] = acc2[i][jj] + bb2;
    }
    __syncthreads();

    // ---- per-row log-softmax NLL (warp 0, one thread per row)
    if (tid < 32) {
        float mx = -1e30f;
        for (int c = 0; c < 128; ++c) mx = fmaxf(mx, zsm[tid][c]);
        float se = 0.0f;
        for (int c = 0; c < 128; ++c) se += expf(zsm[tid][c] - mx);
        float nll = mx + logf(se) - zsm[tid][aid_s[tid]];
        #pragma unroll
        for (int o = 16; o; o >>= 1)
            nll += __shfl_down_sync(0xffffffffu, nll, o);
        if (tid == 0) d_partial[blockIdx.x] = nll;
    }
}

// ===================================================================
// K4: deterministic final reduce
// ===================================================================
__global__ void reduce_k(float* __restrict__ out)
{
    __shared__ float s[256];
    float v = 0.0f;
    for (int i = threadIdx.x; i < 2048; i += 256) v += d_partial[i];
    s[threadIdx.x] = v;
    __syncthreads();
    for (int o = 128; o; o >>= 1) {
        if (threadIdx.x < o) s[threadIdx.x] += s[threadIdx.x + o];
        __syncthreads();
    }
    if (threadIdx.x == 0) out[0] = s[0];
}

// ===================================================================
extern "C" void kernel_launch(void* const* d_in, const int* in_sizes, int n_in,
                              void* d_out, int out_size)
{
    const int*   stack_ids  = (const int*)d_in[0];
    const int*   buffer_ids = (const int*)d_in[1];
    const int*   action_ids = (const int*)d_in[2];
    const float* word_emb   = (const float*)d_in[3];
    const float* action_emb = (const float*)d_in[4];
    const float* Wsx        = (const float*)d_in[5];
    const float* Wsh        = (const float*)d_in[6];
    const float* bs         = (const float*)d_in[7];
    const float* Whx        = (const float*)d_in[8];
    const float* Whh        = (const float*)d_in[9];
    const float* bh         = (const float*)d_in[10];
    const float* W1         = (const float*)d_in[11];
    const float* b1         = (const float*)d_in[12];
    const float* W2         = (const float*)d_in[13];
    const float* b2         = (const float*)d_in[14];
    float* out = (float*)d_out;

    void* barp = nullptr;
    cudaGetSymbolAddress(&barp, d_barrier);
    cudaMemsetAsync(barp, 0, 16 * sizeof(unsigned), 0);

    void* gs = nullptr; void* gh = nullptr;
    cudaGetSymbolAddress(&gs, d_GS);
    cudaGetSymbolAddress(&gh, d_GH);

    // Build per-id preact tables (vocab: 32000 rows; actions: 128 rows)
    dim3 gv(32000 / 128, 16);
    table_gemm<<<gv, 256>>>(word_emb, Wsx, bs, (float*)gs);
    dim3 ga(1, 16);
    table_gemm<<<ga, 256>>>(action_emb, Whx, bh, (float*)gh);

    lstm_rec<<<128, 256>>>(Wsh, Whh, stack_ids, action_ids);
    mlp_nll<<<2048, 256>>>(buffer_ids, action_ids, word_emb, W1, b1, W2, b2);
    reduce_k<<<1, 256>>>(out);
}